// round 16
// baseline (speedup 1.0000x reference)
#include <cuda_runtime.h>
#include <cstdint>

// Fused 3x3 dilate (max) + erode (min), fp32, (8,32,512,512) NCHW.
// Border: reduce over valid pixels only (replication == +/-inf pad).
// Output: [dilated | eroded], each 67108864 floats.
//
// R16: hybrid of the two best-measured mechanisms.
//  - READ side (from R12): 4-deep guard-free ring. Each block owns 4
//    consecutive 8-row chunks of one image (grid 4096); all four 20KB
//    cp.async.bulk reads issued at block start.
//  - WRITE side (from R8/R15, the reproducible e2e winner): outputs
//    staged in smem, emitted as 16KB cp.async.bulk bursts; out-buffer
//    reuse across chunks gated by cp.async.bulk.wait_group.read.
//  - 112KB dynamic smem -> 2 blocks/SM.

#define W 512
#define H 512
#define ROWS_OUT 8
#define ROWS_IN  10
#define THREADS 128
#define CPB 4
#define STAGE_FLOATS (ROWS_IN * W)              // 5120
#define OUT_FLOATS   (ROWS_OUT * W)             // 4096
#define STAGE_BYTES  (STAGE_FLOATS * 4)         // 20480
#define OUT_BYTES    (OUT_FLOATS * 4)           // 16384
#define SMEM_TOTAL   (CPB * STAGE_BYTES + 2 * OUT_BYTES + 64)  // 114752

extern __shared__ float smem_pool[];

__device__ __forceinline__ void mbar_wait0(uint32_t mbar) {
    asm volatile(
        "{\n\t"
        ".reg .pred P;\n\t"
        "WAIT_%=:\n\t"
        "mbarrier.try_wait.parity.shared.b64 P, [%0], 0, 10000000;\n\t"
        "@P bra.uni DONE_%=;\n\t"
        "bra.uni WAIT_%=;\n\t"
        "DONE_%=:\n\t"
        "}"
        :: "r"(mbar) : "memory");
}

__device__ __forceinline__ void bulk_load(uint32_t s_data, const float* src,
                                          uint32_t s_mbar) {
    asm volatile("mbarrier.arrive.expect_tx.shared.b64 _, [%0], %1;"
                 :: "r"(s_mbar), "r"((uint32_t)STAGE_BYTES));
    asm volatile(
        "cp.async.bulk.shared::cluster.global.mbarrier::complete_tx::bytes "
        "[%0], [%1], %2, [%3];"
        :: "r"(s_data), "l"(src), "r"((uint32_t)STAGE_BYTES), "r"(s_mbar)
        : "memory");
}

__device__ __forceinline__ void bulk_store(float* dst, uint32_t s_src) {
    asm volatile(
        "cp.async.bulk.global.shared::cta.bulk_group [%0], [%1], %2;"
        :: "l"(dst), "r"(s_src), "r"((uint32_t)OUT_BYTES) : "memory");
}

// local chunk start row -> clamped input-window start row
__device__ __forceinline__ int clamp_y0(int r0) {
    int y0 = r0 - 1;
    if (y0 < 0) y0 = 0;
    if (y0 > H - ROWS_IN) y0 = H - ROWS_IN;
    return y0;
}

__device__ __forceinline__ void compute_chunk(const float* __restrict__ buf,
                                              int r0, int x4,
                                              float* __restrict__ dout,
                                              float* __restrict__ eout)
{
    const int y0 = clamp_y0(r0);

    auto read_row = [&](int si, float4& v, float& lv, float& rv) {
        const float* rp = buf + si * W;
        v  = *reinterpret_cast<const float4*>(rp + x4);
        lv = (x4 > 0)     ? rp[x4 - 1] : v.x;   // replicate at image edge
        rv = (x4 + 4 < W) ? rp[x4 + 4] : v.w;
    };

    float4 pv, cv, nv;
    float plv, prv, clv, crv, nlv, nrv;

    int sp = r0 - 1 - y0; if (sp < 0) sp = 0;       // replicate top row
    read_row(sp,      pv, plv, prv);
    read_row(r0 - y0, cv, clv, crv);

    #pragma unroll
    for (int i = 0; i < ROWS_OUT; ++i) {
        int sn = r0 + i + 1 - y0;
        if (sn > ROWS_IN - 1) sn = ROWS_IN - 1;     // replicate bottom row
        read_row(sn, nv, nlv, nrv);

        float4 vmn, vmx;
        vmn.x = fminf(pv.x, fminf(cv.x, nv.x));
        vmn.y = fminf(pv.y, fminf(cv.y, nv.y));
        vmn.z = fminf(pv.z, fminf(cv.z, nv.z));
        vmn.w = fminf(pv.w, fminf(cv.w, nv.w));
        vmx.x = fmaxf(pv.x, fmaxf(cv.x, nv.x));
        vmx.y = fmaxf(pv.y, fmaxf(cv.y, nv.y));
        vmx.z = fmaxf(pv.z, fmaxf(cv.z, nv.z));
        vmx.w = fmaxf(pv.w, fmaxf(cv.w, nv.w));

        const float vl_mn = fminf(plv, fminf(clv, nlv));
        const float vl_mx = fmaxf(plv, fmaxf(clv, nlv));
        const float vr_mn = fminf(prv, fminf(crv, nrv));
        const float vr_mx = fmaxf(prv, fmaxf(crv, nrv));

        float4 omin, omax;
        omin.x = fminf(vl_mn, fminf(vmn.x, vmn.y));
        omin.y = fminf(vmn.x, fminf(vmn.y, vmn.z));
        omin.z = fminf(vmn.y, fminf(vmn.z, vmn.w));
        omin.w = fminf(vmn.z, fminf(vmn.w, vr_mn));

        omax.x = fmaxf(vl_mx, fmaxf(vmx.x, vmx.y));
        omax.y = fmaxf(vmx.x, fmaxf(vmx.y, vmx.z));
        omax.z = fmaxf(vmx.y, fmaxf(vmx.z, vmx.w));
        omax.w = fmaxf(vmx.z, fmaxf(vmx.w, vr_mx));

        *reinterpret_cast<float4*>(dout + i * W + x4) = omax;
        *reinterpret_cast<float4*>(eout + i * W + x4) = omin;

        pv = cv; cv = nv;
        plv = clv; clv = nlv;
        prv = crv; crv = nrv;
    }
}

__global__ __launch_bounds__(THREADS)
void erode_dilate_kernel(const float* __restrict__ in,
                         float* __restrict__ dil,
                         float* __restrict__ ero)
{
    float* dout = smem_pool + CPB * STAGE_FLOATS;
    float* eout = dout + OUT_FLOATS;
    uint64_t* mbar = (uint64_t*)(eout + OUT_FLOATS);

    const int tid = threadIdx.x;
    const int x4  = tid * 4;
    const int bid = blockIdx.x;

    // 4 consecutive 8-row chunks of one image; 16 quads per image
    const int img = bid >> 4;
    const int r0  = (bid & 15) * (ROWS_OUT * CPB);

    const size_t ibase = (size_t)img * (H * W);
    const float* base  = in  + ibase;
    float*       dbase = dil + ibase;
    float*       ebase = ero + ibase;

    const uint32_t s_do = (uint32_t)__cvta_generic_to_shared(dout);
    const uint32_t s_eo = (uint32_t)__cvta_generic_to_shared(eout);

    uint32_t s_st[CPB], s_mb[CPB];
    #pragma unroll
    for (int j = 0; j < CPB; ++j) {
        s_st[j] = (uint32_t)__cvta_generic_to_shared(smem_pool + j * STAGE_FLOATS);
        s_mb[j] = (uint32_t)__cvta_generic_to_shared(&mbar[j]);
    }

    if (tid == 0) {
        #pragma unroll
        for (int j = 0; j < CPB; ++j)
            asm volatile("mbarrier.init.shared.b64 [%0], 1;" :: "r"(s_mb[j]));
    }
    __syncthreads();
    if (tid == 0) {
        #pragma unroll
        for (int j = 0; j < CPB; ++j)
            bulk_load(s_st[j], base + (size_t)clamp_y0(r0 + j * ROWS_OUT) * W,
                      s_mb[j]);
    }

    #pragma unroll
    for (int j = 0; j < CPB; ++j) {
        const int rj = r0 + j * ROWS_OUT;

        mbar_wait0(s_mb[j]);
        if (j > 0) {
            // previous chunk's bulk stores must have READ dout/eout
            if (tid == 0)
                asm volatile("cp.async.bulk.wait_group.read 0;" ::: "memory");
            __syncthreads();
        }

        compute_chunk(smem_pool + j * STAGE_FLOATS, rj, x4, dout, eout);
        __syncthreads();                     // all results staged in smem

        if (tid == 0) {
            asm volatile("fence.proxy.async.shared::cta;" ::: "memory");
            bulk_store(dbase + (size_t)rj * W, s_do);
            bulk_store(ebase + (size_t)rj * W, s_eo);
            asm volatile("cp.async.bulk.commit_group;" ::: "memory");
        }
    }

    // smem is freed at CTA exit: last stores must be fully done
    if (tid == 0)
        asm volatile("cp.async.bulk.wait_group 0;" ::: "memory");
}

extern "C" void kernel_launch(void* const* d_in, const int* in_sizes, int n_in,
                              void* d_out, int out_size)
{
    const float* x = (const float*)d_in[0];
    const int n = in_sizes[0];                  // 67108864
    const int nimg = n / (H * W);               // 256

    float* dil = (float*)d_out;
    float* ero = (float*)d_out + n;

    cudaFuncSetAttribute(erode_dilate_kernel,
                         cudaFuncAttributeMaxDynamicSharedMemorySize,
                         SMEM_TOTAL);

    const int nblocks = nimg * (H / (ROWS_OUT * CPB));  // 4096
    erode_dilate_kernel<<<nblocks, THREADS, SMEM_TOTAL>>>(x, dil, ero);
}

// round 17
// speedup vs baseline: 1.0132x; 1.0132x over previous
#include <cuda_runtime.h>
#include <cstdint>

// Fused 3x3 dilate (max) + erode (min), fp32, (8,32,512,512) NCHW.
// Border: reduce over valid pixels only (replication == +/-inf pad).
// Output: [dilated | eroded], each 67108864 floats.
//
// R17 FINAL: the twice-confirmed e2e winner (R8 config: 124.1, 123.5us),
// resubmitted verbatim after the R16 hybrid regressed (125.3us — sharing
// one out-buffer pair across 4 chunks serialized on wait_group.read).
//   Roofline closure: all variants saturate 6.2-6.3 TB/s = LTS cap
//   (~6.9 TB/s) minus mixed 1R:2W turnaround; DRAM traffic at the 768MB
//   compulsory floor. This config's bulk-store epilogue additionally wins
//   ~1.5-2.5us on the scored e2e metric (store drain retired in-kernel).
// Structure:
//  - Non-persistent, 2 chunks/block; both 20KB cp.async.bulk reads issued
//    at block start.
//  - Outputs staged in smem, written as 16KB cp.async.bulk bursts
//    (bulk_group); out-buffer reuse gated by wait_group.read.
//  - 74KB dynamic smem -> 3 blocks/SM; grid 8192.

#define W 512
#define H 512
#define ROWS_OUT 8
#define ROWS_IN  10
#define THREADS 128
#define STAGE_FLOATS (ROWS_IN * W)          // 5120
#define OUT_FLOATS   (ROWS_OUT * W)         // 4096
#define STAGE_BYTES  (STAGE_FLOATS * 4)     // 20480
#define OUT_BYTES    (OUT_FLOATS * 4)       // 16384
#define SMEM_TOTAL   ((2 * STAGE_FLOATS + 2 * OUT_FLOATS) * 4 + 64)

extern __shared__ float smem_pool[];

__device__ __forceinline__ void mbar_wait(uint32_t mbar, uint32_t parity) {
    asm volatile(
        "{\n\t"
        ".reg .pred P;\n\t"
        "WAIT_%=:\n\t"
        "mbarrier.try_wait.parity.shared.b64 P, [%0], %1, 10000000;\n\t"
        "@P bra.uni DONE_%=;\n\t"
        "bra.uni WAIT_%=;\n\t"
        "DONE_%=:\n\t"
        "}"
        :: "r"(mbar), "r"(parity) : "memory");
}

__device__ __forceinline__ void bulk_load(uint32_t s_data, const float* src,
                                          uint32_t s_mbar) {
    asm volatile("mbarrier.arrive.expect_tx.shared.b64 _, [%0], %1;"
                 :: "r"(s_mbar), "r"((uint32_t)STAGE_BYTES));
    asm volatile(
        "cp.async.bulk.shared::cluster.global.mbarrier::complete_tx::bytes "
        "[%0], [%1], %2, [%3];"
        :: "r"(s_data), "l"(src), "r"((uint32_t)STAGE_BYTES), "r"(s_mbar)
        : "memory");
}

__device__ __forceinline__ void bulk_store(float* dst, uint32_t s_src) {
    asm volatile(
        "cp.async.bulk.global.shared::cta.bulk_group [%0], [%1], %2;"
        :: "l"(dst), "r"(s_src), "r"((uint32_t)OUT_BYTES) : "memory");
}

__device__ __forceinline__ void compute_chunk(const float* __restrict__ buf,
                                              int r0, int y0, int x4,
                                              float* __restrict__ dout,
                                              float* __restrict__ eout)
{
    auto read_row = [&](int si, float4& v, float& lv, float& rv) {
        const float* rp = buf + si * W;
        v  = *reinterpret_cast<const float4*>(rp + x4);
        lv = (x4 > 0)     ? rp[x4 - 1] : v.x;   // replicate at image edge
        rv = (x4 + 4 < W) ? rp[x4 + 4] : v.w;
    };

    float4 pv, cv, nv;
    float plv, prv, clv, crv, nlv, nrv;

    int sp = r0 - 1 - y0; if (sp < 0) sp = 0;       // replicate top row
    read_row(sp,      pv, plv, prv);
    read_row(r0 - y0, cv, clv, crv);

    #pragma unroll
    for (int i = 0; i < ROWS_OUT; ++i) {
        int sn = r0 + i + 1 - y0;
        if (sn > ROWS_IN - 1) sn = ROWS_IN - 1;     // replicate bottom row
        read_row(sn, nv, nlv, nrv);

        float4 vmn, vmx;
        vmn.x = fminf(pv.x, fminf(cv.x, nv.x));
        vmn.y = fminf(pv.y, fminf(cv.y, nv.y));
        vmn.z = fminf(pv.z, fminf(cv.z, nv.z));
        vmn.w = fminf(pv.w, fminf(cv.w, nv.w));
        vmx.x = fmaxf(pv.x, fmaxf(cv.x, nv.x));
        vmx.y = fmaxf(pv.y, fmaxf(cv.y, nv.y));
        vmx.z = fmaxf(pv.z, fmaxf(cv.z, nv.z));
        vmx.w = fmaxf(pv.w, fmaxf(cv.w, nv.w));

        const float vl_mn = fminf(plv, fminf(clv, nlv));
        const float vl_mx = fmaxf(plv, fmaxf(clv, nlv));
        const float vr_mn = fminf(prv, fminf(crv, nrv));
        const float vr_mx = fmaxf(prv, fmaxf(crv, nrv));

        float4 omin, omax;
        omin.x = fminf(vl_mn, fminf(vmn.x, vmn.y));
        omin.y = fminf(vmn.x, fminf(vmn.y, vmn.z));
        omin.z = fminf(vmn.y, fminf(vmn.z, vmn.w));
        omin.w = fminf(vmn.z, fminf(vmn.w, vr_mn));

        omax.x = fmaxf(vl_mx, fmaxf(vmx.x, vmx.y));
        omax.y = fmaxf(vmx.x, fmaxf(vmx.y, vmx.z));
        omax.z = fmaxf(vmx.y, fmaxf(vmx.z, vmx.w));
        omax.w = fmaxf(vmx.z, fmaxf(vmx.w, vr_mx));

        *reinterpret_cast<float4*>(dout + i * W + x4) = omax;
        *reinterpret_cast<float4*>(eout + i * W + x4) = omin;

        pv = cv; cv = nv;
        plv = clv; clv = nlv;
        prv = crv; crv = nrv;
    }
}

__global__ __launch_bounds__(THREADS)
void erode_dilate_kernel(const float* __restrict__ in,
                         float* __restrict__ dil,
                         float* __restrict__ ero)
{
    float* stage0 = smem_pool;
    float* stage1 = smem_pool + STAGE_FLOATS;
    float* dout   = smem_pool + 2 * STAGE_FLOATS;
    float* eout   = dout + OUT_FLOATS;
    uint64_t* mbar = (uint64_t*)(eout + OUT_FLOATS);

    const int tid = threadIdx.x;
    const int x4  = tid * 4;
    const int bid = blockIdx.x;

    // two consecutive chunks
    const int c0 = 2 * bid;
    const int img = c0 >> 6;
    const int r0a = (c0 & 63) * ROWS_OUT;
    const int r0b = r0a + ROWS_OUT;

    int y0a = r0a - 1;
    if (y0a < 0) y0a = 0;
    if (y0a > H - ROWS_IN) y0a = H - ROWS_IN;
    int y0b = r0b - 1;
    if (y0b > H - ROWS_IN) y0b = H - ROWS_IN;

    const size_t ibase = (size_t)img * (H * W);
    const float* base  = in  + ibase;
    float*       dbase = dil + ibase;
    float*       ebase = ero + ibase;

    const uint32_t s_st0 = (uint32_t)__cvta_generic_to_shared(stage0);
    const uint32_t s_st1 = (uint32_t)__cvta_generic_to_shared(stage1);
    const uint32_t s_do  = (uint32_t)__cvta_generic_to_shared(dout);
    const uint32_t s_eo  = (uint32_t)__cvta_generic_to_shared(eout);
    const uint32_t s_mb0 = (uint32_t)__cvta_generic_to_shared(&mbar[0]);
    const uint32_t s_mb1 = (uint32_t)__cvta_generic_to_shared(&mbar[1]);

    if (tid == 0) {
        asm volatile("mbarrier.init.shared.b64 [%0], 1;" :: "r"(s_mb0));
        asm volatile("mbarrier.init.shared.b64 [%0], 1;" :: "r"(s_mb1));
    }
    __syncthreads();
    if (tid == 0) {
        bulk_load(s_st0, base + (size_t)y0a * W, s_mb0);
        bulk_load(s_st1, base + (size_t)y0b * W, s_mb1);
    }

    // ---- chunk A ----
    mbar_wait(s_mb0, 0);
    compute_chunk(stage0, r0a, y0a, x4, dout, eout);
    __syncthreads();                         // all results in smem
    if (tid == 0) {
        asm volatile("fence.proxy.async.shared::cta;" ::: "memory");
        bulk_store(dbase + (size_t)r0a * W, s_do);
        bulk_store(ebase + (size_t)r0a * W, s_eo);
        asm volatile("cp.async.bulk.commit_group;" ::: "memory");
    }

    // ---- chunk B ----
    mbar_wait(s_mb1, 0);
    if (tid == 0) {
        // wait until chunk A's stores finished READING the out buffers
        asm volatile("cp.async.bulk.wait_group.read 0;" ::: "memory");
    }
    __syncthreads();                         // gate reuse of dout/eout
    compute_chunk(stage1, r0b, y0b, x4, dout, eout);
    __syncthreads();
    if (tid == 0) {
        asm volatile("fence.proxy.async.shared::cta;" ::: "memory");
        bulk_store(dbase + (size_t)r0b * W, s_do);
        bulk_store(ebase + (size_t)r0b * W, s_eo);
        asm volatile("cp.async.bulk.commit_group;" ::: "memory");
        // smem is freed at CTA exit: stores must be fully done
        asm volatile("cp.async.bulk.wait_group 0;" ::: "memory");
    }
}

extern "C" void kernel_launch(void* const* d_in, const int* in_sizes, int n_in,
                              void* d_out, int out_size)
{
    const float* x = (const float*)d_in[0];
    const int n = in_sizes[0];                  // 67108864
    const int nimg = n / (H * W);               // 256

    float* dil = (float*)d_out;
    float* ero = (float*)d_out + n;

    cudaFuncSetAttribute(erode_dilate_kernel,
                         cudaFuncAttributeMaxDynamicSharedMemorySize,
                         SMEM_TOTAL);

    const int nblocks = nimg * (H / (ROWS_OUT * 2));  // 8192
    erode_dilate_kernel<<<nblocks, THREADS, SMEM_TOTAL>>>(x, dil, ero);
}